// round 6
// baseline (speedup 1.0000x reference)
#include <cuda_runtime.h>
#include <cuda_bf16.h>
#include <cstdint>

#define SDIM 4096
#define DDIM 64
#define TM 128
#define TN 128
#define JSPLIT 4
#define ROWB (SDIM / TM)                     /* 32 */
#define TILES_PER_CTA (SDIM / (TN * JSPLIT)) /* 8 */
#define NCTA (ROWB * JSPLIT)                 /* 128 */
#define NTHREADS 256

// ---- smem layout (224KB) ----
#define SM_QA 0
#define SM_QB (SM_QA + 16384)
#define SM_QC (SM_QB + 16384)
#define SM_KA (SM_QC + 16384)
#define SM_KB (SM_KA + 16384)
#define SM_KC (SM_KB + 16384)
#define SM_VHA (SM_KC + 16384)
#define SM_VLA (SM_VHA + 16384)
#define SM_VHB (SM_VLA + 16384)
#define SM_VLB (SM_VHB + 16384)
#define SM_U   (SM_VLB + 16384)   /* 128 rows x 512B, XOR-swizzled */
#define SMEM_BYTES (SM_U + 65536) /* 229376 */
#define SM_RED SM_KA              /* reused post-loop */

__device__ float g_outpart[JSPLIT][SDIM][DDIM];
__device__ float g_rpart[NCTA];
__device__ int g_arrive = 0;
__device__ int g_depart = 0;

// ---------------- PTX helpers ----------------
__device__ __forceinline__ uint32_t smem_u32(const void* p) {
    uint32_t a;
    asm("{ .reg .u64 t; cvta.to.shared.u64 t, %1; cvt.u32.u64 %0, t; }"
        : "=r"(a) : "l"(p));
    return a;
}
#define LDSM4(d0, d1, d2, d3, a) \
    asm volatile("ldmatrix.sync.aligned.m8n8.x4.shared.b16 {%0,%1,%2,%3}, [%4];" \
                 : "=r"(d0), "=r"(d1), "=r"(d2), "=r"(d3) : "r"(a))
#define LDSM4T(d0, d1, d2, d3, a) \
    asm volatile("ldmatrix.sync.aligned.m8n8.x4.trans.shared.b16 {%0,%1,%2,%3}, [%4];" \
                 : "=r"(d0), "=r"(d1), "=r"(d2), "=r"(d3) : "r"(a))
#define MMA16816(c, a, b0_, b1_) \
    asm volatile("mma.sync.aligned.m16n8k16.row.col.f32.bf16.bf16.f32 " \
                 "{%0,%1,%2,%3}, {%4,%5,%6,%7}, {%8,%9}, {%0,%1,%2,%3};" \
                 : "+f"((c)[0]), "+f"((c)[1]), "+f"((c)[2]), "+f"((c)[3]) \
                 : "r"((a)[0]), "r"((a)[1]), "r"((a)[2]), "r"((a)[3]), \
                   "r"(b0_), "r"(b1_))
#define CVTPK(r, lo, hi) \
    asm("cvt.rn.satfinite.bf16x2.f32 %0, %1, %2;" : "=r"(r) : "f"(hi), "f"(lo))
#define CPASYNC16(dst, src) \
    asm volatile("cp.async.cg.shared.global [%0], [%1], 16;" :: "r"(dst), "l"(src))
#define CPASYNC_COMMIT() asm volatile("cp.async.commit_group;" ::: "memory")
#define CPASYNC_WAIT0()  asm volatile("cp.async.wait_group 0;" ::: "memory")

__device__ __forceinline__ void split3_pair(float x, float y, uint32_t& h,
                                            uint32_t& m, uint32_t& l) {
    CVTPK(h, x, y);
    float rx = x - __uint_as_float(h << 16);
    float ry = y - __uint_as_float(h & 0xffff0000u);
    CVTPK(m, rx, ry);
    float sx = rx - __uint_as_float(m << 16);
    float sy = ry - __uint_as_float(m & 0xffff0000u);
    CVTPK(l, sx, sy);
}
__device__ __forceinline__ void split2_pair(float x, float y, uint32_t& h,
                                            uint32_t& l) {
    CVTPK(h, x, y);
    float rx = x - __uint_as_float(h << 16);
    float ry = y - __uint_as_float(h & 0xffff0000u);
    CVTPK(l, rx, ry);
}

// convert one 1/8 chunk of a K/V tile into split bf16 smem tiles
__device__ __forceinline__ void convert_chunk(char* smem, int tid, int p,
                                              const float4 kv, const float4 vv,
                                              uint32_t vh_off, uint32_t vl_off) {
    int c = tid + p * NTHREADS;
    int row = c >> 4, q4 = (c & 15) * 4;
    uint32_t b = (uint32_t)row * 128 + q4 * 2;
    uint32_t sw = b ^ ((b >> 3) & 0x70);
    uint32_t h01, m01, l01, h23, m23, l23;
    split3_pair(kv.x, kv.y, h01, m01, l01);
    split3_pair(kv.z, kv.w, h23, m23, l23);
    *(uint2*)(smem + SM_KA + sw) = make_uint2(h01, h23);
    *(uint2*)(smem + SM_KB + sw) = make_uint2(m01, m23);
    *(uint2*)(smem + SM_KC + sw) = make_uint2(l01, l23);
    uint32_t vh01, vl01, vh23, vl23;
    split2_pair(vv.x, vv.y, vh01, vl01);
    split2_pair(vv.z, vv.w, vh23, vl23);
    *(uint2*)(smem + vh_off + sw) = make_uint2(vh01, vh23);
    *(uint2*)(smem + vl_off + sw) = make_uint2(vl01, vl23);
}

// ------------------------------ main kernel ------------------------------
__global__ void __launch_bounds__(NTHREADS, 1) fused_attn_main(
    const float* __restrict__ Q, const float* __restrict__ K,
    const float* __restrict__ V, const float* __restrict__ U,
    const float* __restrict__ RR, float* __restrict__ out)
{
    extern __shared__ char smem[];
    const uint32_t sb = smem_u32(smem);
    const int tid = threadIdx.x;
    const int wid = tid >> 5;
    const int l = tid & 31;
    const int wr = wid >> 1;             // 0..3 : 32-row slice of i
    const int wc = wid & 1;              // 0..1 : 64-col slice of j
    const int i0 = blockIdx.y * TM;
    const int jbase = blockIdx.x * (SDIM / JSPLIT);
    const float CF = 8.0f / 0.9f;

    const uint32_t keysw = (uint32_t)(l & 7) << 4;
    const uint32_t rowA = (uint32_t)(l & 15) * 128;
    const uint32_t colA = (uint32_t)((l >> 4) << 4);
    const uint32_t rowB = (uint32_t)((l & 7) + 8 * (l >> 4)) * 128;
    const uint32_t colB = (uint32_t)(((l >> 3) & 1) << 4);

    // ---- prologue: Q split (tile-invariant) ----
#pragma unroll
    for (int p = 0; p < 8; ++p) {
        int c = tid + p * NTHREADS;
        int row = c >> 4, q4 = (c & 15) * 4;
        float4 x = *(const float4*)(Q + (size_t)(i0 + row) * DDIM + q4);
        uint32_t h01, m01, l01, h23, m23, l23;
        split3_pair(x.x, x.y, h01, m01, l01);
        split3_pair(x.z, x.w, h23, m23, l23);
        uint32_t b = (uint32_t)row * 128 + q4 * 2;
        uint32_t sw = b ^ ((b >> 3) & 0x70);
        *(uint2*)(smem + SM_QA + sw) = make_uint2(h01, h23);
        *(uint2*)(smem + SM_QB + sw) = make_uint2(m01, m23);
        *(uint2*)(smem + SM_QC + sw) = make_uint2(l01, l23);
    }
    // ---- prologue: K/V tile 0 convert + U tile 0 cp.async ----
    {
#pragma unroll
        for (int p = 0; p < 8; ++p) {
            int c = tid + p * NTHREADS;
            int row = c >> 4, q4 = (c & 15) * 4;
            float4 kv = *(const float4*)(K + (size_t)(jbase + row) * DDIM + q4);
            float4 vv = *(const float4*)(V + (size_t)(jbase + row) * DDIM + q4);
            convert_chunk(smem, tid, p, kv, vv, SM_VHA, SM_VLA);
        }
#pragma unroll
        for (int p = 0; p < 16; ++p) {
            int c = tid + p * NTHREADS;
            int r = c >> 5, col16 = c & 31;
            uint32_t dst = sb + SM_U + (uint32_t)r * 512 +
                           (((uint32_t)col16 << 4) ^ (((uint32_t)r & 7) << 4));
            const float* src = U + (size_t)(i0 + r) * SDIM + jbase + col16 * 4;
            CPASYNC16(dst, src);
        }
        CPASYNC_COMMIT();
    }

    float rr0[2], rr1[2];
#pragma unroll
    for (int mt = 0; mt < 2; ++mt) {
        rr0[mt] = RR[i0 + 32 * wr + 16 * mt + (l >> 2)];
        rr1[mt] = RR[i0 + 32 * wr + 16 * mt + 8 + (l >> 2)];
    }

    float oacc[2][8][4];
#pragma unroll
    for (int mt = 0; mt < 2; ++mt)
#pragma unroll
        for (int dt = 0; dt < 8; ++dt)
#pragma unroll
            for (int e = 0; e < 4; ++e) oacc[mt][dt][e] = 0.0f;
    float rsum = 0.0f;

#pragma unroll 1
    for (int jt = 0; jt < TILES_PER_CTA; ++jt) {
        const uint32_t vrd_h = (jt & 1) ? SM_VHB : SM_VHA;
        const uint32_t vrd_l = (jt & 1) ? SM_VLB : SM_VLA;
        const uint32_t vwr_h = (jt & 1) ? SM_VHA : SM_VHB;
        const uint32_t vwr_l = (jt & 1) ? SM_VLA : SM_VLB;
        const int j0n = jbase + (jt + 1) * TN;   // next tile base
        const bool more = (jt + 1 < TILES_PER_CTA);

        __syncthreads();  // (C) convert(t) STS visible to all warps

        // -- GEMM1: S = 6 split products --
        float sacc[2][8][4];
#pragma unroll
        for (int mt = 0; mt < 2; ++mt)
#pragma unroll
            for (int nt = 0; nt < 8; ++nt)
#pragma unroll
                for (int e = 0; e < 4; ++e) sacc[mt][nt][e] = 0.0f;

#pragma unroll
        for (int kt = 0; kt < 4; ++kt) {
            uint32_t amat3[3][2][4];
#pragma unroll
            for (int pa = 0; pa < 3; ++pa)
#pragma unroll
                for (int mt = 0; mt < 2; ++mt) {
                    uint32_t addr = sb + SM_QA + (uint32_t)pa * 16384 +
                                    (uint32_t)(32 * wr + 16 * mt) * 128 +
                                    rowA + (((uint32_t)kt * 32 + colA) ^ keysw);
                    LDSM4(amat3[pa][mt][0], amat3[pa][mt][1], amat3[pa][mt][2],
                          amat3[pa][mt][3], addr);
                }
#pragma unroll
            for (int pb = 0; pb < 3; ++pb) {
                uint32_t bm[8][2];
#pragma unroll
                for (int u = 0; u < 4; ++u) {
                    uint32_t addr = sb + SM_KA + (uint32_t)pb * 16384 +
                                    (uint32_t)(64 * wc + 16 * u) * 128 +
                                    rowB + (((uint32_t)kt * 32 + colB) ^ keysw);
                    LDSM4(bm[2 * u][0], bm[2 * u][1], bm[2 * u + 1][0],
                          bm[2 * u + 1][1], addr);
                }
                const int npa = 3 - pb;
#pragma unroll
                for (int pa = 0; pa < 3; ++pa) {
                    if (pa >= npa) break;
#pragma unroll
                    for (int mt = 0; mt < 2; ++mt)
#pragma unroll
                        for (int nt = 0; nt < 8; ++nt)
                            MMA16816(sacc[mt][nt], amat3[pa][mt], bm[nt][0],
                                     bm[nt][1]);
                }
            }
        }

        CPASYNC_WAIT0();
        __syncthreads();  // (A) U(t) visible CTA-wide

        // -- elementwise: U from smem; build GEMM2 A-fragments --
        uint32_t aH[2][4][4], aL[2][4][4];
#pragma unroll
        for (int mt = 0; mt < 2; ++mt) {
            const int rl = 32 * wr + 16 * mt + (l >> 2);
            const uint32_t ukey = (((uint32_t)(l >> 2)) & 7) << 4;
            const uint32_t cbase = (uint32_t)(256 * wc + (l & 3) * 8);
            float2 u0v[8], u1v[8];
#pragma unroll
            for (int nt = 0; nt < 8; ++nt) {
                uint32_t cb = cbase + 32 * nt;
                u0v[nt] = *(const float2*)(smem + SM_U + (uint32_t)rl * 512 +
                                           (cb ^ ukey));
                u1v[nt] = *(const float2*)(smem + SM_U + (uint32_t)(rl + 8) * 512 +
                                           (cb ^ ukey));
            }
            const float ra = rr0[mt], rb = rr1[mt];
#pragma unroll
            for (int nt = 0; nt < 8; ++nt) {
                float t0 = (u0v[nt].x >= 0.1f) ? sacc[mt][nt][0] * CF : 0.0f;
                float t1 = (u0v[nt].y >= 0.1f) ? sacc[mt][nt][1] * CF : 0.0f;
                float t2 = (u1v[nt].x >= 0.1f) ? sacc[mt][nt][2] * CF : 0.0f;
                float t3 = (u1v[nt].y >= 0.1f) ? sacc[mt][nt][3] * CF : 0.0f;
                float r0 = floorf(t0 * ra), r1 = floorf(t1 * ra);
                float r2 = floorf(t2 * rb), r3 = floorf(t3 * rb);
                rsum += (r0 + r1) + (r2 + r3);
                float tr0 = t0 * r0, tr1 = t1 * r1, tr2 = t2 * r2, tr3 = t3 * r3;
                uint32_t h01, lo01, h23, lo23;
                split2_pair(tr0, tr1, h01, lo01);
                split2_pair(tr2, tr3, h23, lo23);
                const int kt2 = nt >> 1, sub = (nt & 1) * 2;
                aH[mt][kt2][sub] = h01; aH[mt][kt2][sub + 1] = h23;
                aL[mt][kt2][sub] = lo01; aL[mt][kt2][sub + 1] = lo23;
            }
        }

        __syncthreads();  // (B) U reads + GEMM1 ldsm done: U/K/V bufs reusable

        // -- stage next tile's K/V (regs) and U (cp.async) --
        float4 kreg[8], vreg[8];
        if (more) {
#pragma unroll
            for (int p = 0; p < 8; ++p) {
                int c = tid + p * NTHREADS;
                int row = c >> 4, q4 = (c & 15) * 4;
                kreg[p] = *(const float4*)(K + (size_t)(j0n + row) * DDIM + q4);
                vreg[p] = *(const float4*)(V + (size_t)(j0n + row) * DDIM + q4);
            }
#pragma unroll
            for (int p = 0; p < 16; ++p) {
                int c = tid + p * NTHREADS;
                int r = c >> 5, col16 = c & 31;
                uint32_t dst = sb + SM_U + (uint32_t)r * 512 +
                               (((uint32_t)col16 << 4) ^ (((uint32_t)r & 7) << 4));
                const float* src = U + (size_t)(i0 + r) * SDIM + j0n + col16 * 4;
                CPASYNC16(dst, src);
            }
            CPASYNC_COMMIT();
        }

        // -- merged: GEMM2(t) interleaved with convert(t+1) --
#pragma unroll
        for (int kt = 0; kt < 4; ++kt) {
            uint32_t bmh[8][2];
#pragma unroll
            for (int u = 0; u < 4; ++u) {
                uint32_t addr = sb + vrd_h + (uint32_t)(64 * wc + 16 * kt) * 128 +
                                rowA + (((uint32_t)u * 32 + colA) ^ keysw);
                LDSM4T(bmh[2 * u][0], bmh[2 * u][1], bmh[2 * u + 1][0],
                       bmh[2 * u + 1][1], addr);
            }
            if (more)
                convert_chunk(smem, tid, 2 * kt, kreg[2 * kt], vreg[2 * kt],
                              vwr_h, vwr_l);
#pragma unroll
            for (int mt = 0; mt < 2; ++mt)
#pragma unroll
                for (int dt = 0; dt < 8; ++dt)
                    MMA16816(oacc[mt][dt], aH[mt][kt], bmh[dt][0], bmh[dt][1]);
#pragma unroll
            for (int mt = 0; mt < 2; ++mt)
#pragma unroll
                for (int dt = 0; dt < 8; ++dt)
                    MMA16816(oacc[mt][dt], aL[mt][kt], bmh[dt][0], bmh[dt][1]);
            uint32_t bml[8][2];
#pragma unroll
            for (int u = 0; u < 4; ++u) {
                uint32_t addr = sb + vrd_l + (uint32_t)(64 * wc + 16 * kt) * 128 +
                                rowA + (((uint32_t)u * 32 + colA) ^ keysw);
                LDSM4T(bml[2 * u][0], bml[2 * u][1], bml[2 * u + 1][0],
                       bml[2 * u + 1][1], addr);
            }
            if (more)
                convert_chunk(smem, tid, 2 * kt + 1, kreg[2 * kt + 1],
                              vreg[2 * kt + 1], vwr_h, vwr_l);
#pragma unroll
            for (int mt = 0; mt < 2; ++mt)
#pragma unroll
                for (int dt = 0; dt < 8; ++dt)
                    MMA16816(oacc[mt][dt], aH[mt][kt], bml[dt][0], bml[dt][1]);
        }
    }

    // ---- cross-warp (wc) reduction of output partials via smem ----
    __syncthreads();
    float* rbuf = (float*)smem;
    if (wc == 1) {
#pragma unroll
        for (int mt = 0; mt < 2; ++mt)
#pragma unroll
            for (int dt = 0; dt < 8; ++dt)
#pragma unroll
                for (int e = 0; e < 4; ++e)
                    rbuf[wr * 2048 + ((mt * 8 + dt) * 4 + e) * 32 + l] =
                        oacc[mt][dt][e];
    }
    __syncthreads();
    if (wc == 0) {
#pragma unroll
        for (int mt = 0; mt < 2; ++mt)
#pragma unroll
            for (int dt = 0; dt < 8; ++dt) {
                float c0 = oacc[mt][dt][0] +
                           rbuf[wr * 2048 + ((mt * 8 + dt) * 4 + 0) * 32 + l];
                float c1 = oacc[mt][dt][1] +
                           rbuf[wr * 2048 + ((mt * 8 + dt) * 4 + 1) * 32 + l];
                float c2 = oacc[mt][dt][2] +
                           rbuf[wr * 2048 + ((mt * 8 + dt) * 4 + 2) * 32 + l];
                float c3 = oacc[mt][dt][3] +
                           rbuf[wr * 2048 + ((mt * 8 + dt) * 4 + 3) * 32 + l];
                int r0 = i0 + 32 * wr + 16 * mt + (l >> 2);
                int col = 8 * dt + (l & 3) * 2;
                *(float2*)(&g_outpart[blockIdx.x][r0][col]) = make_float2(c0, c1);
                *(float2*)(&g_outpart[blockIdx.x][r0 + 8][col]) = make_float2(c2, c3);
            }
    }

    // ---- deterministic rsum reduction ----
#pragma unroll
    for (int off = 16; off; off >>= 1)
        rsum += __shfl_xor_sync(0xffffffffu, rsum, off);
    float* red = (float*)(smem + SM_RED);
    __syncthreads();
    if (l == 0) red[wid] = rsum;
    __syncthreads();
    if (tid == 0) {
        float tot = 0.0f;
#pragma unroll
        for (int w = 0; w < 8; ++w) tot += red[w];
        g_rpart[blockIdx.y * JSPLIT + blockIdx.x] = tot;
    }

    // ---- device-wide barrier (128 CTAs all co-resident: 224KB smem => 1/SM) ----
    __threadfence();
    __syncthreads();
    if (tid == 0) atomicAdd(&g_arrive, 1);

    if (blockIdx.x == 0) {
        if (tid == 0) {
            while (atomicAdd(&g_arrive, 0) < NCTA) __nanosleep(64);
            __threadfence();
        }
        __syncthreads();
        float* red2 = (float*)smem;
        if (tid < NCTA) red2[tid] = __ldcg(&g_rpart[tid]);
        __syncthreads();
#pragma unroll
        for (int s = 64; s > 0; s >>= 1) {
            if (tid < s) red2[tid] += red2[tid + s];
            __syncthreads();
        }
        const float R = red2[0];
        const float* base = &g_outpart[0][0][0];
        const size_t part = (size_t)SDIM * DDIM;
        const size_t rowbase = (size_t)i0 * DDIM / 4;
#pragma unroll
        for (int p = 0; p < 8; ++p) {
            size_t idx = rowbase + (size_t)p * NTHREADS + tid;
            float4 a = __ldcg((const float4*)(base + idx * 4));
            float4 b = __ldcg((const float4*)(base + part + idx * 4));
            float4 c = __ldcg((const float4*)(base + 2 * part + idx * 4));
            float4 d = __ldcg((const float4*)(base + 3 * part + idx * 4));
            float4 o;
            o.x = (((a.x + b.x) + c.x) + d.x) / R;
            o.y = (((a.y + b.y) + c.y) + d.y) / R;
            o.z = (((a.z + b.z) + c.z) + d.z) / R;
            o.w = (((a.w + b.w) + c.w) + d.w) / R;
            *(float4*)(out + idx * 4) = o;
        }
    }

    __syncthreads();
    if (tid == 0) {
        int old = atomicAdd(&g_depart, 1);
        if (old == NCTA - 1) {
            atomicExch(&g_arrive, 0);
            atomicExch(&g_depart, 0);
            __threadfence();
        }
    }
}

extern "C" void kernel_launch(void* const* d_in, const int* in_sizes, int n_in,
                              void* d_out, int out_size)
{
    const float* Q  = (const float*)d_in[0];
    const float* K  = (const float*)d_in[1];
    const float* V  = (const float*)d_in[2];
    const float* U  = (const float*)d_in[3];
    const float* RR = (const float*)d_in[4];
    float* out = (float*)d_out;

    cudaFuncSetAttribute(fused_attn_main,
                         cudaFuncAttributeMaxDynamicSharedMemorySize, SMEM_BYTES);

    dim3 grid(JSPLIT, ROWB);
    fused_attn_main<<<grid, NTHREADS, SMEM_BYTES>>>(Q, K, V, U, RR, out);
}

// round 7
// speedup vs baseline: 1.0735x; 1.0735x over previous
#include <cuda_runtime.h>
#include <cuda_bf16.h>
#include <cstdint>

#define SDIM 4096
#define DDIM 64
#define TM 128
#define TN 128
#define JSPLIT 4
#define ROWB (SDIM / TM)                     /* 32 */
#define TILES_PER_CTA (SDIM / (TN * JSPLIT)) /* 8 */
#define NCTA (ROWB * JSPLIT)                 /* 128 */
#define NTHREADS 256

// ---- smem: 8 bf16 split tiles + U stage ----
#define SM_QA 0
#define SM_QB (SM_QA + 16384)
#define SM_QC (SM_QB + 16384)
#define SM_KA (SM_QC + 16384)
#define SM_KB (SM_KA + 16384)
#define SM_KC (SM_KB + 16384)
#define SM_VH (SM_KC + 16384)
#define SM_VL (SM_VH + 16384)
#define SM_U  (SM_VL + 16384)     /* 128 rows x 512B, XOR-swizzled */
#define SMEM_BYTES (SM_U + 65536) /* 196608 */
#define SM_RED SM_KA              /* reused post-loop for reductions */

__device__ float g_outpart[JSPLIT][SDIM][DDIM];
__device__ float g_rpart[NCTA];
__device__ int g_arrive = 0;
__device__ int g_depart = 0;

// ---------------- PTX helpers (baseline sm_80/90 features only) ----------------
__device__ __forceinline__ uint32_t smem_u32(const void* p) {
    uint32_t a;
    asm("{ .reg .u64 t; cvta.to.shared.u64 t, %1; cvt.u32.u64 %0, t; }"
        : "=r"(a) : "l"(p));
    return a;
}
#define LDSM4(d0, d1, d2, d3, a) \
    asm volatile("ldmatrix.sync.aligned.m8n8.x4.shared.b16 {%0,%1,%2,%3}, [%4];" \
                 : "=r"(d0), "=r"(d1), "=r"(d2), "=r"(d3) : "r"(a))
#define LDSM4T(d0, d1, d2, d3, a) \
    asm volatile("ldmatrix.sync.aligned.m8n8.x4.trans.shared.b16 {%0,%1,%2,%3}, [%4];" \
                 : "=r"(d0), "=r"(d1), "=r"(d2), "=r"(d3) : "r"(a))
#define MMA16816(c, a, b0_, b1_) \
    asm volatile("mma.sync.aligned.m16n8k16.row.col.f32.bf16.bf16.f32 " \
                 "{%0,%1,%2,%3}, {%4,%5,%6,%7}, {%8,%9}, {%0,%1,%2,%3};" \
                 : "+f"((c)[0]), "+f"((c)[1]), "+f"((c)[2]), "+f"((c)[3]) \
                 : "r"((a)[0]), "r"((a)[1]), "r"((a)[2]), "r"((a)[3]), \
                   "r"(b0_), "r"(b1_))
#define CVTPK(r, lo, hi) \
    asm("cvt.rn.satfinite.bf16x2.f32 %0, %1, %2;" : "=r"(r) : "f"(hi), "f"(lo))
#define CPASYNC16(dst, src) \
    asm volatile("cp.async.cg.shared.global [%0], [%1], 16;" :: "r"(dst), "l"(src))
#define CPASYNC_COMMIT() asm volatile("cp.async.commit_group;" ::: "memory")
#define CPASYNC_WAIT0()  asm volatile("cp.async.wait_group 0;" ::: "memory")

__device__ __forceinline__ void split3_pair(float x, float y, uint32_t& h,
                                            uint32_t& m, uint32_t& l) {
    CVTPK(h, x, y);
    float rx = x - __uint_as_float(h << 16);
    float ry = y - __uint_as_float(h & 0xffff0000u);
    CVTPK(m, rx, ry);
    float sx = rx - __uint_as_float(m << 16);
    float sy = ry - __uint_as_float(m & 0xffff0000u);
    CVTPK(l, sx, sy);
}
__device__ __forceinline__ void split2_pair(float x, float y, uint32_t& h,
                                            uint32_t& l) {
    CVTPK(h, x, y);
    float rx = x - __uint_as_float(h << 16);
    float ry = y - __uint_as_float(h & 0xffff0000u);
    CVTPK(l, rx, ry);
}

// ------------------------------ main kernel ------------------------------
__global__ void __launch_bounds__(NTHREADS, 1) fused_attn_main(
    const float* __restrict__ Q, const float* __restrict__ K,
    const float* __restrict__ V, const float* __restrict__ U,
    const float* __restrict__ RR, float* __restrict__ out)
{
    extern __shared__ char smem[];
    const uint32_t sb = smem_u32(smem);
    const int tid = threadIdx.x;
    const int wid = tid >> 5;
    const int l = tid & 31;
    const int wr = wid >> 1;             // 0..3 : 32-row slice of i
    const int wc = wid & 1;              // 0..1 : 64-col slice of j (k-split)
    const int i0 = blockIdx.y * TM;
    const int jbase = blockIdx.x * (SDIM / JSPLIT);
    const float CF = 8.0f / 0.9f;

    // per-lane ldmatrix address components (128B rows, XOR swizzle key)
    const uint32_t keysw = (uint32_t)(l & 7) << 4;
    const uint32_t rowA = (uint32_t)(l & 15) * 128;            // Q / V patterns
    const uint32_t colA = (uint32_t)((l >> 4) << 4);
    const uint32_t rowB = (uint32_t)((l & 7) + 8 * (l >> 4)) * 128;  // K pattern
    const uint32_t colB = (uint32_t)(((l >> 3) & 1) << 4);

    // ---- Q -> 3-way bf16 split smem (once; tile-invariant) ----
#pragma unroll
    for (int p = 0; p < 8; ++p) {
        int c = tid + p * NTHREADS;          // float4 index, 0..2047
        int row = c >> 4, q4 = (c & 15) * 4;
        float4 x = *(const float4*)(Q + (size_t)(i0 + row) * DDIM + q4);
        uint32_t h01, m01, l01, h23, m23, l23;
        split3_pair(x.x, x.y, h01, m01, l01);
        split3_pair(x.z, x.w, h23, m23, l23);
        uint32_t b = (uint32_t)row * 128 + q4 * 2;
        uint32_t sw = b ^ ((b >> 3) & 0x70);
        *(uint2*)(smem + SM_QA + sw) = make_uint2(h01, h23);
        *(uint2*)(smem + SM_QB + sw) = make_uint2(m01, m23);
        *(uint2*)(smem + SM_QC + sw) = make_uint2(l01, l23);
    }

    float rr0[2], rr1[2];
#pragma unroll
    for (int mt = 0; mt < 2; ++mt) {
        rr0[mt] = RR[i0 + 32 * wr + 16 * mt + (l >> 2)];
        rr1[mt] = RR[i0 + 32 * wr + 16 * mt + 8 + (l >> 2)];
    }

    float oacc[2][8][4];
#pragma unroll
    for (int mt = 0; mt < 2; ++mt)
#pragma unroll
        for (int dt = 0; dt < 8; ++dt)
#pragma unroll
            for (int e = 0; e < 4; ++e) oacc[mt][dt][e] = 0.0f;
    float rsum = 0.0f;

#pragma unroll 1
    for (int jt = 0; jt < TILES_PER_CTA; ++jt) {
        const int j0 = jbase + jt * TN;

        // -- prefetch K/V tile into registers --
        float4 kreg[8], vreg[8];
#pragma unroll
        for (int p = 0; p < 8; ++p) {
            int c = tid + p * NTHREADS;
            int row = c >> 4, q4 = (c & 15) * 4;
            kreg[p] = *(const float4*)(K + (size_t)(j0 + row) * DDIM + q4);
            vreg[p] = *(const float4*)(V + (size_t)(j0 + row) * DDIM + q4);
        }
        __syncthreads();  // previous tile's ldsm / U-stage reads complete

        // -- stage U(t) into smem via cp.async (hidden under convert+GEMM1) --
#pragma unroll
        for (int p = 0; p < 16; ++p) {
            int c = tid + p * NTHREADS;
            int r = c >> 5, col16 = c & 31;
            uint32_t dst = sb + SM_U + (uint32_t)r * 512 +
                           (((uint32_t)col16 << 4) ^ (((uint32_t)r & 7) << 4));
            const float* src = U + (size_t)(i0 + r) * SDIM + j0 + col16 * 4;
            CPASYNC16(dst, src);
        }
        CPASYNC_COMMIT();

        // -- split-store K (3-way) and V (2-way) --
#pragma unroll
        for (int p = 0; p < 8; ++p) {
            int c = tid + p * NTHREADS;
            int row = c >> 4, q4 = (c & 15) * 4;
            uint32_t b = (uint32_t)row * 128 + q4 * 2;
            uint32_t sw = b ^ ((b >> 3) & 0x70);
            uint32_t h01, m01, l01, h23, m23, l23;
            split3_pair(kreg[p].x, kreg[p].y, h01, m01, l01);
            split3_pair(kreg[p].z, kreg[p].w, h23, m23, l23);
            *(uint2*)(smem + SM_KA + sw) = make_uint2(h01, h23);
            *(uint2*)(smem + SM_KB + sw) = make_uint2(m01, m23);
            *(uint2*)(smem + SM_KC + sw) = make_uint2(l01, l23);
            uint32_t vh01, vl01, vh23, vl23;
            split2_pair(vreg[p].x, vreg[p].y, vh01, vl01);
            split2_pair(vreg[p].z, vreg[p].w, vh23, vl23);
            *(uint2*)(smem + SM_VH + sw) = make_uint2(vh01, vh23);
            *(uint2*)(smem + SM_VL + sw) = make_uint2(vl01, vl23);
        }
        __syncthreads();

        // -- GEMM1: S = 6 split products; A/B fragments hoisted per kt --
        float sacc[2][8][4];
#pragma unroll
        for (int mt = 0; mt < 2; ++mt)
#pragma unroll
            for (int nt = 0; nt < 8; ++nt)
#pragma unroll
                for (int e = 0; e < 4; ++e) sacc[mt][nt][e] = 0.0f;

#pragma unroll
        for (int kt = 0; kt < 4; ++kt) {
            uint32_t amat3[3][2][4];
#pragma unroll
            for (int pa = 0; pa < 3; ++pa)
#pragma unroll
                for (int mt = 0; mt < 2; ++mt) {
                    uint32_t addr = sb + SM_QA + (uint32_t)pa * 16384 +
                                    (uint32_t)(32 * wr + 16 * mt) * 128 +
                                    rowA + (((uint32_t)kt * 32 + colA) ^ keysw);
                    LDSM4(amat3[pa][mt][0], amat3[pa][mt][1], amat3[pa][mt][2],
                          amat3[pa][mt][3], addr);
                }
            // kept (pa,pb): pb=0 -> pa{0,1,2}; pb=1 -> pa{0,1}; pb=2 -> pa{0}
#pragma unroll
            for (int pb = 0; pb < 3; ++pb) {
                uint32_t bm[8][2];
#pragma unroll
                for (int u = 0; u < 4; ++u) {
                    uint32_t addr = sb + SM_KA + (uint32_t)pb * 16384 +
                                    (uint32_t)(64 * wc + 16 * u) * 128 +
                                    rowB + (((uint32_t)kt * 32 + colB) ^ keysw);
                    LDSM4(bm[2 * u][0], bm[2 * u][1], bm[2 * u + 1][0],
                          bm[2 * u + 1][1], addr);
                }
                const int npa = 3 - pb;
#pragma unroll
                for (int pa = 0; pa < 3; ++pa) {
                    if (pa >= npa) break;
#pragma unroll
                    for (int mt = 0; mt < 2; ++mt)
#pragma unroll
                        for (int nt = 0; nt < 8; ++nt)
                            MMA16816(sacc[mt][nt], amat3[pa][mt], bm[nt][0],
                                     bm[nt][1]);
                }
            }
        }

        CPASYNC_WAIT0();
        __syncthreads();  // U(t) visible CTA-wide

        // -- elementwise: U from smem; build GEMM2 A-fragments in registers --
        uint32_t aH[2][4][4], aL[2][4][4];
#pragma unroll
        for (int mt = 0; mt < 2; ++mt) {
            const int rl = 32 * wr + 16 * mt + (l >> 2);
            const uint32_t ukey = (((uint32_t)(l >> 2)) & 7) << 4;
            const uint32_t cbase = (uint32_t)(256 * wc + (l & 3) * 8);
            float2 u0v[8], u1v[8];
#pragma unroll
            for (int nt = 0; nt < 8; ++nt) {
                uint32_t cb = cbase + 32 * nt;
                u0v[nt] = *(const float2*)(smem + SM_U + (uint32_t)rl * 512 +
                                           (cb ^ ukey));
                u1v[nt] = *(const float2*)(smem + SM_U + (uint32_t)(rl + 8) * 512 +
                                           (cb ^ ukey));
            }
            const float ra = rr0[mt], rb = rr1[mt];
#pragma unroll
            for (int nt = 0; nt < 8; ++nt) {
                float t0 = (u0v[nt].x >= 0.1f) ? sacc[mt][nt][0] * CF : 0.0f;
                float t1 = (u0v[nt].y >= 0.1f) ? sacc[mt][nt][1] * CF : 0.0f;
                float t2 = (u1v[nt].x >= 0.1f) ? sacc[mt][nt][2] * CF : 0.0f;
                float t3 = (u1v[nt].y >= 0.1f) ? sacc[mt][nt][3] * CF : 0.0f;
                float r0 = floorf(t0 * ra), r1 = floorf(t1 * ra);
                float r2 = floorf(t2 * rb), r3 = floorf(t3 * rb);
                rsum += (r0 + r1) + (r2 + r3);
                float tr0 = t0 * r0, tr1 = t1 * r1, tr2 = t2 * r2, tr3 = t3 * r3;
                uint32_t h01, lo01, h23, lo23;
                split2_pair(tr0, tr1, h01, lo01);
                split2_pair(tr2, tr3, h23, lo23);
                const int kt2 = nt >> 1, sub = (nt & 1) * 2;
                aH[mt][kt2][sub] = h01; aH[mt][kt2][sub + 1] = h23;
                aL[mt][kt2][sub] = lo01; aL[mt][kt2][sub + 1] = lo23;
            }
        }

        // -- GEMM2: oacc += TRH*VH + TRL*VH + TRH*VL ; VH hoisted per kt --
#pragma unroll
        for (int kt = 0; kt < 4; ++kt) {
            uint32_t bmh[8][2];
#pragma unroll
            for (int u = 0; u < 4; ++u) {
                uint32_t addr = sb + SM_VH + (uint32_t)(64 * wc + 16 * kt) * 128 +
                                rowA + (((uint32_t)u * 32 + colA) ^ keysw);
                LDSM4T(bmh[2 * u][0], bmh[2 * u][1], bmh[2 * u + 1][0],
                       bmh[2 * u + 1][1], addr);
            }
#pragma unroll
            for (int mt = 0; mt < 2; ++mt)
#pragma unroll
                for (int dt = 0; dt < 8; ++dt)
                    MMA16816(oacc[mt][dt], aH[mt][kt], bmh[dt][0], bmh[dt][1]);
#pragma unroll
            for (int mt = 0; mt < 2; ++mt)
#pragma unroll
                for (int dt = 0; dt < 8; ++dt)
                    MMA16816(oacc[mt][dt], aL[mt][kt], bmh[dt][0], bmh[dt][1]);
            uint32_t bml[8][2];
#pragma unroll
            for (int u = 0; u < 4; ++u) {
                uint32_t addr = sb + SM_VL + (uint32_t)(64 * wc + 16 * kt) * 128 +
                                rowA + (((uint32_t)u * 32 + colA) ^ keysw);
                LDSM4T(bml[2 * u][0], bml[2 * u][1], bml[2 * u + 1][0],
                       bml[2 * u + 1][1], addr);
            }
#pragma unroll
            for (int mt = 0; mt < 2; ++mt)
#pragma unroll
                for (int dt = 0; dt < 8; ++dt)
                    MMA16816(oacc[mt][dt], aH[mt][kt], bml[dt][0], bml[dt][1]);
        }
    }

    // ---- cross-warp (wc) reduction of output partials via smem ----
    __syncthreads();
    float* rbuf = (float*)smem;
    if (wc == 1) {
#pragma unroll
        for (int mt = 0; mt < 2; ++mt)
#pragma unroll
            for (int dt = 0; dt < 8; ++dt)
#pragma unroll
                for (int e = 0; e < 4; ++e)
                    rbuf[wr * 2048 + ((mt * 8 + dt) * 4 + e) * 32 + l] =
                        oacc[mt][dt][e];
    }
    __syncthreads();
    if (wc == 0) {
#pragma unroll
        for (int mt = 0; mt < 2; ++mt)
#pragma unroll
            for (int dt = 0; dt < 8; ++dt) {
                float c0 = oacc[mt][dt][0] +
                           rbuf[wr * 2048 + ((mt * 8 + dt) * 4 + 0) * 32 + l];
                float c1 = oacc[mt][dt][1] +
                           rbuf[wr * 2048 + ((mt * 8 + dt) * 4 + 1) * 32 + l];
                float c2 = oacc[mt][dt][2] +
                           rbuf[wr * 2048 + ((mt * 8 + dt) * 4 + 2) * 32 + l];
                float c3 = oacc[mt][dt][3] +
                           rbuf[wr * 2048 + ((mt * 8 + dt) * 4 + 3) * 32 + l];
                int r0 = i0 + 32 * wr + 16 * mt + (l >> 2);
                int col = 8 * dt + (l & 3) * 2;
                *(float2*)(&g_outpart[blockIdx.x][r0][col]) = make_float2(c0, c1);
                *(float2*)(&g_outpart[blockIdx.x][r0 + 8][col]) = make_float2(c2, c3);
            }
    }

    // ---- deterministic rsum reduction ----
#pragma unroll
    for (int off = 16; off; off >>= 1)
        rsum += __shfl_xor_sync(0xffffffffu, rsum, off);
    float* red = (float*)(smem + SM_RED);
    __syncthreads();
    if (l == 0) red[wid] = rsum;
    __syncthreads();
    if (tid == 0) {
        float tot = 0.0f;
#pragma unroll
        for (int w = 0; w < 8; ++w) tot += red[w];
        g_rpart[blockIdx.y * JSPLIT + blockIdx.x] = tot;
    }

    // ---- device-wide barrier (128 CTAs all co-resident: 192KB smem => 1/SM) ----
    __threadfence();
    __syncthreads();
    if (tid == 0) atomicAdd(&g_arrive, 1);

    if (blockIdx.x == 0) {
        if (tid == 0) {
            while (atomicAdd(&g_arrive, 0) < NCTA) __nanosleep(64);
            __threadfence();
        }
        __syncthreads();
        float* red2 = (float*)smem;
        if (tid < NCTA) red2[tid] = __ldcg(&g_rpart[tid]);
        __syncthreads();
#pragma unroll
        for (int s = 64; s > 0; s >>= 1) {
            if (tid < s) red2[tid] += red2[tid + s];
            __syncthreads();
        }
        const float R = red2[0];
        const float* base = &g_outpart[0][0][0];
        const size_t part = (size_t)SDIM * DDIM;
        const size_t rowbase = (size_t)i0 * DDIM / 4;
#pragma unroll
        for (int p = 0; p < 8; ++p) {
            size_t idx = rowbase + (size_t)p * NTHREADS + tid;
            float4 a = __ldcg((const float4*)(base + idx * 4));
            float4 b = __ldcg((const float4*)(base + part + idx * 4));
            float4 c = __ldcg((const float4*)(base + 2 * part + idx * 4));
            float4 d = __ldcg((const float4*)(base + 3 * part + idx * 4));
            float4 o;
            o.x = (((a.x + b.x) + c.x) + d.x) / R;
            o.y = (((a.y + b.y) + c.y) + d.y) / R;
            o.z = (((a.z + b.z) + c.z) + d.z) / R;
            o.w = (((a.w + b.w) + c.w) + d.w) / R;
            *(float4*)(out + idx * 4) = o;
        }
    }

    __syncthreads();
    if (tid == 0) {
        int old = atomicAdd(&g_depart, 1);
        if (old == NCTA - 1) {
            atomicExch(&g_arrive, 0);
            atomicExch(&g_depart, 0);
            __threadfence();
        }
    }
}

extern "C" void kernel_launch(void* const* d_in, const int* in_sizes, int n_in,
                              void* d_out, int out_size)
{
    const float* Q  = (const float*)d_in[0];
    const float* K  = (const float*)d_in[1];
    const float* V  = (const float*)d_in[2];
    const float* U  = (const float*)d_in[3];
    const float* RR = (const float*)d_in[4];
    float* out = (float*)d_out;

    cudaFuncSetAttribute(fused_attn_main,
                         cudaFuncAttributeMaxDynamicSharedMemorySize, SMEM_BYTES);

    dim3 grid(JSPLIT, ROWB);
    fused_attn_main<<<grid, NTHREADS, SMEM_BYTES>>>(Q, K, V, U, RR, out);
}

// round 8
// speedup vs baseline: 1.1546x; 1.0755x over previous
#include <cuda_runtime.h>
#include <cuda_bf16.h>
#include <cstdint>

#define SDIM 4096
#define DDIM 64
#define TM 128
#define TN 128
#define JSPLIT 4
#define ROWB (SDIM / TM)                     /* 32 */
#define TILES_PER_CTA (SDIM / (TN * JSPLIT)) /* 8 */
#define NCTA (ROWB * JSPLIT)                 /* 128 */
#define NTHREADS 512

// ---- smem: 8 bf16 split tiles of [128][64], 128B rows, XOR-swizzled ----
#define SM_QA 0
#define SM_QB (SM_QA + 16384)
#define SM_QC (SM_QB + 16384)
#define SM_KA (SM_QC + 16384)
#define SM_KB (SM_KA + 16384)
#define SM_KC (SM_KB + 16384)
#define SM_VH (SM_KC + 16384)
#define SM_VL (SM_VH + 16384)
#define SMEM_BYTES (SM_VL + 16384)  /* 131072 */
#define SM_RED SM_KA                /* reused post-loop for reductions */

__device__ float g_outpart[JSPLIT][SDIM][DDIM];
__device__ float g_rpart[NCTA];
__device__ int g_arrive = 0;
__device__ int g_depart = 0;

// ---------------- PTX helpers (baseline sm_80/90 features only) ----------------
__device__ __forceinline__ uint32_t smem_u32(const void* p) {
    uint32_t a;
    asm("{ .reg .u64 t; cvta.to.shared.u64 t, %1; cvt.u32.u64 %0, t; }"
        : "=r"(a) : "l"(p));
    return a;
}
#define LDSM4(d0, d1, d2, d3, a) \
    asm volatile("ldmatrix.sync.aligned.m8n8.x4.shared.b16 {%0,%1,%2,%3}, [%4];" \
                 : "=r"(d0), "=r"(d1), "=r"(d2), "=r"(d3) : "r"(a))
#define LDSM4T(d0, d1, d2, d3, a) \
    asm volatile("ldmatrix.sync.aligned.m8n8.x4.trans.shared.b16 {%0,%1,%2,%3}, [%4];" \
                 : "=r"(d0), "=r"(d1), "=r"(d2), "=r"(d3) : "r"(a))
#define MMA16816(c, a, b0_, b1_) \
    asm volatile("mma.sync.aligned.m16n8k16.row.col.f32.bf16.bf16.f32 " \
                 "{%0,%1,%2,%3}, {%4,%5,%6,%7}, {%8,%9}, {%0,%1,%2,%3};" \
                 : "+f"((c)[0]), "+f"((c)[1]), "+f"((c)[2]), "+f"((c)[3]) \
                 : "r"((a)[0]), "r"((a)[1]), "r"((a)[2]), "r"((a)[3]), \
                   "r"(b0_), "r"(b1_))
#define CVTPK(r, lo, hi) \
    asm("cvt.rn.satfinite.bf16x2.f32 %0, %1, %2;" : "=r"(r) : "f"(hi), "f"(lo))

__device__ __forceinline__ void split3_pair(float x, float y, uint32_t& h,
                                            uint32_t& m, uint32_t& l) {
    CVTPK(h, x, y);
    float rx = x - __uint_as_float(h << 16);
    float ry = y - __uint_as_float(h & 0xffff0000u);
    CVTPK(m, rx, ry);
    float sx = rx - __uint_as_float(m << 16);
    float sy = ry - __uint_as_float(m & 0xffff0000u);
    CVTPK(l, sx, sy);
}
__device__ __forceinline__ void split2_pair(float x, float y, uint32_t& h,
                                            uint32_t& l) {
    CVTPK(h, x, y);
    float rx = x - __uint_as_float(h << 16);
    float ry = y - __uint_as_float(h & 0xffff0000u);
    CVTPK(l, rx, ry);
}

// ------------------------------ main kernel ------------------------------
__global__ void __launch_bounds__(NTHREADS, 1) fused_attn_main(
    const float* __restrict__ Q, const float* __restrict__ K,
    const float* __restrict__ V, const float* __restrict__ U,
    const float* __restrict__ RR, float* __restrict__ out)
{
    extern __shared__ char smem[];
    const uint32_t sb = smem_u32(smem);
    const int tid = threadIdx.x;
    const int wid = tid >> 5;
    const int l = tid & 31;
    const int wr = wid >> 1;             // 0..7 : 16-row slice of i
    const int wc = wid & 1;              // 0..1 : 64-col slice of j (k-split)
    const int i0 = blockIdx.y * TM;
    const int jbase = blockIdx.x * (SDIM / JSPLIT);
    const float CF = 8.0f / 0.9f;

    // per-lane ldmatrix address components (128B rows, XOR swizzle key)
    const uint32_t keysw = (uint32_t)(l & 7) << 4;
    const uint32_t rowA = (uint32_t)(l & 15) * 128;            // Q / V patterns
    const uint32_t colA = (uint32_t)((l >> 4) << 4);
    const uint32_t rowB = (uint32_t)((l & 7) + 8 * (l >> 4)) * 128;  // K pattern
    const uint32_t colB = (uint32_t)(((l >> 3) & 1) << 4);

    // ---- Q -> 3-way bf16 split smem (once; tile-invariant) ----
#pragma unroll
    for (int p = 0; p < 4; ++p) {
        int c = tid + p * NTHREADS;          // float4 index, 0..2047
        int row = c >> 4, q4 = (c & 15) * 4;
        float4 x = *(const float4*)(Q + (size_t)(i0 + row) * DDIM + q4);
        uint32_t h01, m01, l01, h23, m23, l23;
        split3_pair(x.x, x.y, h01, m01, l01);
        split3_pair(x.z, x.w, h23, m23, l23);
        uint32_t b = (uint32_t)row * 128 + q4 * 2;
        uint32_t sw = b ^ ((b >> 3) & 0x70);
        *(uint2*)(smem + SM_QA + sw) = make_uint2(h01, h23);
        *(uint2*)(smem + SM_QB + sw) = make_uint2(m01, m23);
        *(uint2*)(smem + SM_QC + sw) = make_uint2(l01, l23);
    }

    const float rr0 = RR[i0 + 16 * wr + (l >> 2)];
    const float rr1 = RR[i0 + 16 * wr + 8 + (l >> 2)];

    float oacc[8][4];
#pragma unroll
    for (int dt = 0; dt < 8; ++dt)
#pragma unroll
        for (int e = 0; e < 4; ++e) oacc[dt][e] = 0.0f;
    float rsum = 0.0f;

#pragma unroll 1
    for (int jt = 0; jt < TILES_PER_CTA; ++jt) {
        const int j0 = jbase + jt * TN;

        // -- prefetch K/V tile into registers --
        float4 kreg[4], vreg[4];
#pragma unroll
        for (int p = 0; p < 4; ++p) {
            int c = tid + p * NTHREADS;
            int row = c >> 4, q4 = (c & 15) * 4;
            kreg[p] = *(const float4*)(K + (size_t)(j0 + row) * DDIM + q4);
            vreg[p] = *(const float4*)(V + (size_t)(j0 + row) * DDIM + q4);
        }
        __syncthreads();  // previous tile's ldmatrix reads complete

        // -- split-store K (3-way) and V (2-way) --
#pragma unroll
        for (int p = 0; p < 4; ++p) {
            int c = tid + p * NTHREADS;
            int row = c >> 4, q4 = (c & 15) * 4;
            uint32_t b = (uint32_t)row * 128 + q4 * 2;
            uint32_t sw = b ^ ((b >> 3) & 0x70);
            uint32_t h01, m01, l01, h23, m23, l23;
            split3_pair(kreg[p].x, kreg[p].y, h01, m01, l01);
            split3_pair(kreg[p].z, kreg[p].w, h23, m23, l23);
            *(uint2*)(smem + SM_KA + sw) = make_uint2(h01, h23);
            *(uint2*)(smem + SM_KB + sw) = make_uint2(m01, m23);
            *(uint2*)(smem + SM_KC + sw) = make_uint2(l01, l23);
            uint32_t vh01, vl01, vh23, vl23;
            split2_pair(vreg[p].x, vreg[p].y, vh01, vl01);
            split2_pair(vreg[p].z, vreg[p].w, vh23, vl23);
            *(uint2*)(smem + SM_VH + sw) = make_uint2(vh01, vh23);
            *(uint2*)(smem + SM_VL + sw) = make_uint2(vl01, vl23);
        }
        __syncthreads();

        // -- GEMM1: S = 6 split products; warp patch 16x64 --
        float sacc[8][4];
#pragma unroll
        for (int nt = 0; nt < 8; ++nt)
#pragma unroll
            for (int e = 0; e < 4; ++e) sacc[nt][e] = 0.0f;

#pragma unroll
        for (int kt = 0; kt < 4; ++kt) {
            uint32_t amat3[3][4];
#pragma unroll
            for (int pa = 0; pa < 3; ++pa) {
                uint32_t addr = sb + SM_QA + (uint32_t)pa * 16384 +
                                (uint32_t)(16 * wr) * 128 +
                                rowA + (((uint32_t)kt * 32 + colA) ^ keysw);
                LDSM4(amat3[pa][0], amat3[pa][1], amat3[pa][2], amat3[pa][3],
                      addr);
            }
            // kept (pa,pb): pb=0 -> pa{0,1,2}; pb=1 -> pa{0,1}; pb=2 -> pa{0}
#pragma unroll
            for (int pb = 0; pb < 3; ++pb) {
                uint32_t bm[8][2];
#pragma unroll
                for (int u = 0; u < 4; ++u) {
                    uint32_t addr = sb + SM_KA + (uint32_t)pb * 16384 +
                                    (uint32_t)(64 * wc + 16 * u) * 128 +
                                    rowB + (((uint32_t)kt * 32 + colB) ^ keysw);
                    LDSM4(bm[2 * u][0], bm[2 * u][1], bm[2 * u + 1][0],
                          bm[2 * u + 1][1], addr);
                }
                const int npa = 3 - pb;
#pragma unroll
                for (int pa = 0; pa < 3; ++pa) {
                    if (pa >= npa) break;
#pragma unroll
                    for (int nt = 0; nt < 8; ++nt)
                        MMA16816(sacc[nt], amat3[pa], bm[nt][0], bm[nt][1]);
                }
            }
        }

        // -- elementwise: dropout, floor mask, rsum; build GEMM2 A-fragments --
        uint32_t aH[4][4], aL[4][4];
        {
            const float* u0p = U + (size_t)(i0 + 16 * wr + (l >> 2)) * SDIM +
                               j0 + 64 * wc + (l & 3) * 2;
            const float* u1p = u0p + 8 * SDIM;
#pragma unroll
            for (int nt = 0; nt < 8; ++nt) {
                float2 u0v = *(const float2*)(u0p + 8 * nt);
                float2 u1v = *(const float2*)(u1p + 8 * nt);
                float t0 = (u0v.x >= 0.1f) ? sacc[nt][0] * CF : 0.0f;
                float t1 = (u0v.y >= 0.1f) ? sacc[nt][1] * CF : 0.0f;
                float t2 = (u1v.x >= 0.1f) ? sacc[nt][2] * CF : 0.0f;
                float t3 = (u1v.y >= 0.1f) ? sacc[nt][3] * CF : 0.0f;
                float r0 = floorf(t0 * rr0), r1 = floorf(t1 * rr0);
                float r2 = floorf(t2 * rr1), r3 = floorf(t3 * rr1);
                rsum += (r0 + r1) + (r2 + r3);
                float tr0 = t0 * r0, tr1 = t1 * r1, tr2 = t2 * r2, tr3 = t3 * r3;
                uint32_t h01, lo01, h23, lo23;
                split2_pair(tr0, tr1, h01, lo01);
                split2_pair(tr2, tr3, h23, lo23);
                const int kt2 = nt >> 1, sub = (nt & 1) * 2;
                aH[kt2][sub] = h01; aH[kt2][sub + 1] = h23;
                aL[kt2][sub] = lo01; aL[kt2][sub + 1] = lo23;
            }
        }

        // -- GEMM2: oacc += TRH*VH + TRL*VH + TRH*VL ; VH hoisted per kt --
#pragma unroll
        for (int kt = 0; kt < 4; ++kt) {
            uint32_t bmh[8][2];
#pragma unroll
            for (int u = 0; u < 4; ++u) {
                uint32_t addr = sb + SM_VH + (uint32_t)(64 * wc + 16 * kt) * 128 +
                                rowA + (((uint32_t)u * 32 + colA) ^ keysw);
                LDSM4T(bmh[2 * u][0], bmh[2 * u][1], bmh[2 * u + 1][0],
                       bmh[2 * u + 1][1], addr);
            }
#pragma unroll
            for (int dt = 0; dt < 8; ++dt)
                MMA16816(oacc[dt], aH[kt], bmh[dt][0], bmh[dt][1]);
#pragma unroll
            for (int dt = 0; dt < 8; ++dt)
                MMA16816(oacc[dt], aL[kt], bmh[dt][0], bmh[dt][1]);
            uint32_t bml[8][2];
#pragma unroll
            for (int u = 0; u < 4; ++u) {
                uint32_t addr = sb + SM_VL + (uint32_t)(64 * wc + 16 * kt) * 128 +
                                rowA + (((uint32_t)u * 32 + colA) ^ keysw);
                LDSM4T(bml[2 * u][0], bml[2 * u][1], bml[2 * u + 1][0],
                       bml[2 * u + 1][1], addr);
            }
#pragma unroll
            for (int dt = 0; dt < 8; ++dt)
                MMA16816(oacc[dt], aH[kt], bml[dt][0], bml[dt][1]);
        }
    }

    // ---- cross-warp (wc) reduction of output partials via smem ----
    __syncthreads();
    float* rbuf = (float*)smem;  // 8 warps x 1024 floats = 32KB at SM_QA
    if (wc == 1) {
#pragma unroll
        for (int dt = 0; dt < 8; ++dt)
#pragma unroll
            for (int e = 0; e < 4; ++e)
                rbuf[wr * 1024 + (dt * 4 + e) * 32 + l] = oacc[dt][e];
    }
    __syncthreads();
    if (wc == 0) {
#pragma unroll
        for (int dt = 0; dt < 8; ++dt) {
            float c0 = oacc[dt][0] + rbuf[wr * 1024 + (dt * 4 + 0) * 32 + l];
            float c1 = oacc[dt][1] + rbuf[wr * 1024 + (dt * 4 + 1) * 32 + l];
            float c2 = oacc[dt][2] + rbuf[wr * 1024 + (dt * 4 + 2) * 32 + l];
            float c3 = oacc[dt][3] + rbuf[wr * 1024 + (dt * 4 + 3) * 32 + l];
            int r0 = i0 + 16 * wr + (l >> 2);
            int col = 8 * dt + (l & 3) * 2;
            *(float2*)(&g_outpart[blockIdx.x][r0][col]) = make_float2(c0, c1);
            *(float2*)(&g_outpart[blockIdx.x][r0 + 8][col]) = make_float2(c2, c3);
        }
    }

    // ---- deterministic rsum reduction ----
#pragma unroll
    for (int off = 16; off; off >>= 1)
        rsum += __shfl_xor_sync(0xffffffffu, rsum, off);
    float* red = (float*)(smem + SM_RED);
    __syncthreads();
    if (l == 0) red[wid] = rsum;
    __syncthreads();
    if (tid == 0) {
        float tot = 0.0f;
#pragma unroll
        for (int w = 0; w < 16; ++w) tot += red[w];
        g_rpart[blockIdx.y * JSPLIT + blockIdx.x] = tot;
    }

    // ---- device-wide barrier (128 CTAs all co-resident: 128KB smem => 1/SM) ----
    __threadfence();
    __syncthreads();
    if (tid == 0) atomicAdd(&g_arrive, 1);

    if (blockIdx.x == 0) {
        if (tid == 0) {
            while (atomicAdd(&g_arrive, 0) < NCTA) __nanosleep(64);
            __threadfence();
        }
        __syncthreads();
        float* red2 = (float*)smem;
        if (tid < NCTA) red2[tid] = __ldcg(&g_rpart[tid]);
        __syncthreads();
#pragma unroll
        for (int s = 64; s > 0; s >>= 1) {
            if (tid < s) red2[tid] += red2[tid + s];
            __syncthreads();
        }
        const float R = red2[0];
        const float* base = &g_outpart[0][0][0];
        const size_t part = (size_t)SDIM * DDIM;
        const size_t rowbase = (size_t)i0 * DDIM / 4;
#pragma unroll
        for (int p = 0; p < 4; ++p) {
            size_t idx = rowbase + (size_t)p * NTHREADS + tid;
            float4 a = __ldcg((const float4*)(base + idx * 4));
            float4 b = __ldcg((const float4*)(base + part + idx * 4));
            float4 c = __ldcg((const float4*)(base + 2 * part + idx * 4));
            float4 d = __ldcg((const float4*)(base + 3 * part + idx * 4));
            float4 o;
            o.x = (((a.x + b.x) + c.x) + d.x) / R;
            o.y = (((a.y + b.y) + c.y) + d.y) / R;
            o.z = (((a.z + b.z) + c.z) + d.z) / R;
            o.w = (((a.w + b.w) + c.w) + d.w) / R;
            *(float4*)(out + idx * 4) = o;
        }
    }

    __syncthreads();
    if (tid == 0) {
        int old = atomicAdd(&g_depart, 1);
        if (old == NCTA - 1) {
            atomicExch(&g_arrive, 0);
            atomicExch(&g_depart, 0);
            __threadfence();
        }
    }
}

extern "C" void kernel_launch(void* const* d_in, const int* in_sizes, int n_in,
                              void* d_out, int out_size)
{
    const float* Q  = (const float*)d_in[0];
    const float* K  = (const float*)d_in[1];
    const float* V  = (const float*)d_in[2];
    const float* U  = (const float*)d_in[3];
    const float* RR = (const float*)d_in[4];
    float* out = (float*)d_out;

    cudaFuncSetAttribute(fused_attn_main,
                         cudaFuncAttributeMaxDynamicSharedMemorySize, SMEM_BYTES);

    dim3 grid(JSPLIT, ROWB);
    fused_attn_main<<<grid, NTHREADS, SMEM_BYTES>>>(Q, K, V, U, RR, out);
}